// round 11
// baseline (speedup 1.0000x reference)
#include <cuda_runtime.h>
#include <cuda_fp16.h>
#include <cstdint>
#include <cstddef>

#define TT   512
#define MB   32
#define NTH  512
#define GRID 128

// ---- shared memory byte offsets (h tiles: 32 rows x 64 units fp16, 128B rows, XOR-swizzled) ----
#define H0HI(b) ((b) ? 8192 : 0)
#define H0LO(b) ((b) ? 12288 : 4096)
#define H1HI(b) (16384 + ((b) ? 8192 : 0))
#define H1LO(b) (20480 + ((b) ? 8192 : 0))
#define XOFF(b) (32768 + (b) * 4096)
#define SMEMB   40960

__device__ __forceinline__ uint32_t smem_u32(const void* p) {
    uint32_t a;
    asm("{ .reg .u64 t; cvta.to.shared.u64 t, %1; cvt.u32.u64 %0, t; }" : "=r"(a) : "l"(p));
    return a;
}
__device__ __forceinline__ void ldmA(uint32_t* a, uint32_t saddr) {
    asm volatile("ldmatrix.sync.aligned.m8n8.x4.shared.b16 {%0,%1,%2,%3}, [%4];"
                 : "=r"(a[0]), "=r"(a[1]), "=r"(a[2]), "=r"(a[3]) : "r"(saddr));
}
__device__ __forceinline__ void mma16816(float* d, const uint32_t* a, const uint32_t* b) {
    asm volatile("mma.sync.aligned.m16n8k16.row.col.f32.f16.f16.f32 "
                 "{%0,%1,%2,%3}, {%4,%5,%6,%7}, {%8,%9}, {%0,%1,%2,%3};"
                 : "+f"(d[0]), "+f"(d[1]), "+f"(d[2]), "+f"(d[3])
                 : "r"(a[0]), "r"(a[1]), "r"(a[2]), "r"(a[3]), "r"(b[0]), "r"(b[1]));
}
__device__ __forceinline__ uint32_t f2h2(float a, float b) {
    __half2 h = __floats2half2_rn(a, b);
    return *reinterpret_cast<uint32_t*>(&h);
}
__device__ __forceinline__ float sigm(float x) {
    float e = __expf(-x);
    return __fdividef(1.0f, 1.0f + e);
}
__device__ __forceinline__ float tanh_f(float x) { return fmaf(2.0f, sigm(2.0f * x), -1.0f); }

__global__ void __launch_bounds__(NTH, 1) lstm2_hmma(
    const float* __restrict__ x,
    const float* __restrict__ Wih0, const float* __restrict__ Whh0,
    const float* __restrict__ bih0, const float* __restrict__ bhh0,
    const float* __restrict__ Wih1, const float* __restrict__ Whh1,
    const float* __restrict__ bih1, const float* __restrict__ bhh1,
    const float* __restrict__ Wfc,  const float* __restrict__ bfc,
    float* __restrict__ out)
{
    __shared__ __align__(16) char sm[SMEMB];
    const uint32_t smb = smem_u32(sm);
    const int tid  = threadIdx.x;
    const int wid  = tid >> 5;          // 0..15, owns 16 gate columns
    const int lane = tid & 31;
    const int tg   = lane & 3;
    const int q    = lane >> 2;
    const int odd  = tg & 1;
    const int batch0 = blockIdx.x * MB;

    // ---- zero h + x regions ----
    for (int i = tid; i < SMEMB / 16; i += NTH) ((uint4*)sm)[i] = make_uint4(0, 0, 0, 0);

    // ---- weight B-fragments into registers (one-time, fp16) ----
    const int n_l = lane >> 2;
    uint32_t Bhh0[4][2][2], Bih1[4][2][2], Bhh1[4][2][2], Bx[2][2];
#pragma unroll
    for (int nt = 0; nt < 2; nt++) {
        const int cg = wid * 16 + nt * 8 + n_l;      // global gate column 0..255
        const int u = cg >> 2, g = cg & 3;
        const float* r0 = Whh0 + (g * 64 + u) * 64;
        const float* r1 = Wih1 + (g * 64 + u) * 64;
        const float* r2 = Whh1 + (g * 64 + u) * 64;
#pragma unroll
        for (int kt = 0; kt < 4; kt++) {
            const int k0 = kt * 16 + tg * 2;
            Bhh0[kt][nt][0] = f2h2(r0[k0],     r0[k0 + 1]);
            Bhh0[kt][nt][1] = f2h2(r0[k0 + 8], r0[k0 + 9]);
            Bih1[kt][nt][0] = f2h2(r1[k0],     r1[k0 + 1]);
            Bih1[kt][nt][1] = f2h2(r1[k0 + 8], r1[k0 + 9]);
            Bhh1[kt][nt][0] = f2h2(r2[k0],     r2[k0 + 1]);
            Bhh1[kt][nt][1] = f2h2(r2[k0 + 8], r2[k0 + 9]);
        }
        const float* rx = Wih0 + (g * 64 + u) * 6;
        const int k0 = tg * 2;
        float w0 = (k0     < 6) ? rx[k0]     : 0.0f;
        float w1 = (k0 + 1 < 6) ? rx[k0 + 1] : 0.0f;
        Bx[nt][0] = f2h2(w0, w1);
        Bx[nt][1] = 0u;
    }
    float b0r[4], b1r[4];
#pragma unroll
    for (int nt = 0; nt < 2; nt++) {
#pragma unroll
        for (int j = 0; j < 2; j++) {
            const int cg = wid * 16 + nt * 8 + tg * 2 + j;
            const int u = cg >> 2, g = cg & 3, idx = g * 64 + u;
            b0r[nt * 2 + j] = bih0[idx] + bhh0[idx];
            b1r[nt * 2 + j] = bih1[idx] + bhh1[idx];
        }
    }

    // ---- stage x(0) ----
    if (tid < MB) {
        const float2* xp = (const float2*)(x + (size_t)(batch0 + tid) * TT * 6);
        float2 a = xp[0], b = xp[1], c = xp[2];
        char* p = sm + XOFF(0) + tid * 128 + ((tid & 7) << 4);
        ((uint32_t*)p)[0] = f2h2(a.x, a.y);
        ((uint32_t*)p)[1] = f2h2(b.x, b.y);
        ((uint32_t*)p)[2] = f2h2(c.x, c.y);
    }
    __syncthreads();

    // ldmatrix lane addressing (A 16x16 tiles from 32x64 fp16, 128B rows, XOR swizzle)
    const uint32_t laneRow  = (uint32_t)(lane & 15);
    const uint32_t sw       = (uint32_t)((lane & 7) << 4);
    const uint32_t col16    = (uint32_t)(lane & 16);
    const uint32_t laneTerm = laneRow * 128;

    float cst0[4], cst1[4];
#pragma unroll
    for (int i = 0; i < 4; i++) { cst0[i] = 0.0f; cst1[i] = 0.0f; }

    float acc[2][2][4];

    for (int t = 0; t < TT; t++) {
        const int cur = t & 1, prv = cur ^ 1;

        // prefetch x(t+1)
        float2 xa, xb, xc;
        if (tid < MB && t + 1 < TT) {
            const float2* xp = (const float2*)(x + ((size_t)(batch0 + tid) * TT + (t + 1)) * 6);
            xa = xp[0]; xb = xp[1]; xc = xp[2];
        }

        // ================= layer 0 =================
#pragma unroll
        for (int mt = 0; mt < 2; mt++)
#pragma unroll
            for (int nt = 0; nt < 2; nt++) {
                acc[mt][nt][0] = b0r[nt * 2];     acc[mt][nt][1] = b0r[nt * 2 + 1];
                acc[mt][nt][2] = b0r[nt * 2];     acc[mt][nt][3] = b0r[nt * 2 + 1];
            }
#pragma unroll
        for (int pass = 0; pass < 2; pass++) {
            const uint32_t hb = smb + (pass == 0 ? (uint32_t)H0HI(prv) : (uint32_t)H0LO(prv)) + laneTerm;
#pragma unroll
            for (int kt = 0; kt < 4; kt++) {
                uint32_t a0[4], a1[4];
                const uint32_t coff = (uint32_t)((kt * 32 + col16)) ^ sw;
                ldmA(a0, hb + coff);
                ldmA(a1, hb + 2048 + coff);
#pragma unroll
                for (int nt = 0; nt < 2; nt++) {
                    mma16816(acc[0][nt], a0, Bhh0[kt][nt]);
                    mma16816(acc[1][nt], a1, Bhh0[kt][nt]);
                }
            }
        }
        {   // x contribution (k-tile 0 only)
            const uint32_t xb_ = smb + (uint32_t)XOFF(cur) + laneTerm;
            uint32_t a0[4], a1[4];
            const uint32_t coff = col16 ^ sw;
            ldmA(a0, xb_ + coff);
            ldmA(a1, xb_ + 2048 + coff);
#pragma unroll
            for (int nt = 0; nt < 2; nt++) {
                mma16816(acc[0][nt], a0, Bx[nt]);
                mma16816(acc[1][nt], a1, Bx[nt]);
            }
        }
        // epilogue 0 -> h0[cur]
#pragma unroll
        for (int mt = 0; mt < 2; mt++)
#pragma unroll
            for (int nt = 0; nt < 2; nt++) {
                float* d = acc[mt][nt];
                float s0 = odd ? d[0] : d[2];
                float s1 = odd ? d[1] : d[3];
                float r0 = __shfl_xor_sync(0xffffffffu, s0, 1);
                float r1 = __shfl_xor_sync(0xffffffffu, s1, 1);
                float gi = odd ? r0 : d[0], gf = odd ? r1 : d[1];
                float gg = odd ? d[2] : r0, go = odd ? d[3] : r1;
                float i_ = sigm(gi), f_ = sigm(gf), g_ = tanh_f(gg), o_ = sigm(go);
                float c = fmaf(f_, cst0[mt * 2 + nt], i_ * g_);
                cst0[mt * 2 + nt] = c;
                float h = o_ * tanh_f(c);
                const int u   = wid * 4 + nt * 2 + (tg >> 1);
                const int row = mt * 16 + q + odd * 8;
                const int bo  = row * 128 + ((u * 2) ^ ((row & 7) << 4));
                __half hh = __float2half_rn(h);
                __half hl = __float2half_rn(h - __half2float(hh));
                *(__half*)(sm + H0HI(cur) + bo) = hh;
                *(__half*)(sm + H0LO(cur) + bo) = hl;
            }
        if (tid < MB && t + 1 < TT) {   // publish x(t+1)
            char* p = sm + XOFF(prv) + tid * 128 + ((tid & 7) << 4);
            ((uint32_t*)p)[0] = f2h2(xa.x, xa.y);
            ((uint32_t*)p)[1] = f2h2(xb.x, xb.y);
            ((uint32_t*)p)[2] = f2h2(xc.x, xc.y);
        }
        __syncthreads();

        // ================= layer 1 =================
#pragma unroll
        for (int mt = 0; mt < 2; mt++)
#pragma unroll
            for (int nt = 0; nt < 2; nt++) {
                acc[mt][nt][0] = b1r[nt * 2];     acc[mt][nt][1] = b1r[nt * 2 + 1];
                acc[mt][nt][2] = b1r[nt * 2];     acc[mt][nt][3] = b1r[nt * 2 + 1];
            }
#pragma unroll
        for (int pass = 0; pass < 4; pass++) {
            uint32_t hoff;
            if      (pass == 0) hoff = (uint32_t)H0HI(cur);
            else if (pass == 1) hoff = (uint32_t)H0LO(cur);
            else if (pass == 2) hoff = (uint32_t)H1HI(prv);
            else                hoff = (uint32_t)H1LO(prv);
            const uint32_t hb = smb + hoff + laneTerm;
#pragma unroll
            for (int kt = 0; kt < 4; kt++) {
                uint32_t a0[4], a1[4];
                const uint32_t coff = (uint32_t)((kt * 32 + col16)) ^ sw;
                ldmA(a0, hb + coff);
                ldmA(a1, hb + 2048 + coff);
#pragma unroll
                for (int nt = 0; nt < 2; nt++) {
                    const uint32_t* B = (pass < 2) ? Bih1[kt][nt] : Bhh1[kt][nt];
                    mma16816(acc[0][nt], a0, B);
                    mma16816(acc[1][nt], a1, B);
                }
            }
        }
        // epilogue 1 -> h1[cur]
#pragma unroll
        for (int mt = 0; mt < 2; mt++)
#pragma unroll
            for (int nt = 0; nt < 2; nt++) {
                float* d = acc[mt][nt];
                float s0 = odd ? d[0] : d[2];
                float s1 = odd ? d[1] : d[3];
                float r0 = __shfl_xor_sync(0xffffffffu, s0, 1);
                float r1 = __shfl_xor_sync(0xffffffffu, s1, 1);
                float gi = odd ? r0 : d[0], gf = odd ? r1 : d[1];
                float gg = odd ? d[2] : r0, go = odd ? d[3] : r1;
                float i_ = sigm(gi), f_ = sigm(gf), g_ = tanh_f(gg), o_ = sigm(go);
                float c = fmaf(f_, cst1[mt * 2 + nt], i_ * g_);
                cst1[mt * 2 + nt] = c;
                float h = o_ * tanh_f(c);
                const int u   = wid * 4 + nt * 2 + (tg >> 1);
                const int row = mt * 16 + q + odd * 8;
                const int bo  = row * 128 + ((u * 2) ^ ((row & 7) << 4));
                __half hh = __float2half_rn(h);
                __half hl = __float2half_rn(h - __half2float(hh));
                *(__half*)(sm + H1HI(cur) + bo) = hh;
                *(__half*)(sm + H1LO(cur) + bo) = hl;
            }
        __syncthreads();
    }

    // ---- final FC from h1[(TT-1)&1 = 1]: out = h1 @ Wfc^T + bfc ----
    if (tid < MB * 3) {
        const int b = tid / 3, oc = tid - b * 3;
        float s = bfc[oc];
#pragma unroll 8
        for (int u = 0; u < 64; u++) {
            const int bo = b * 128 + ((u * 2) ^ ((b & 7) << 4));
            float h = __half2float(*(const __half*)(sm + H1HI(1) + bo))
                    + __half2float(*(const __half*)(sm + H1LO(1) + bo));
            s = fmaf(h, Wfc[oc * 64 + u], s);
        }
        out[(size_t)(batch0 + b) * 3 + oc] = s;
    }
}

extern "C" void kernel_launch(void* const* d_in, const int* in_sizes, int n_in,
                              void* d_out, int out_size)
{
    (void)in_sizes; (void)n_in; (void)out_size;
    lstm2_hmma<<<GRID, NTH>>>(
        (const float*)d_in[0],
        (const float*)d_in[1], (const float*)d_in[2],
        (const float*)d_in[3], (const float*)d_in[4],
        (const float*)d_in[5], (const float*)d_in[6],
        (const float*)d_in[7], (const float*)d_in[8],
        (const float*)d_in[9], (const float*)d_in[10],
        (float*)d_out);
}

// round 12
// speedup vs baseline: 1.7525x; 1.7525x over previous
#include <cuda_runtime.h>
#include <cuda_fp16.h>
#include <cstdint>
#include <cstddef>

#define TT   512
#define MB   32
#define NTH  512
#define GRID 128

// ---- shared memory byte offsets (h tiles: 32 rows x 64 units fp16, 128B rows, XOR-swizzled) ----
#define H0OF(b) ((b) * 4096)
#define H1OF(b) (8192 + (b) * 4096)
#define XOFF(b) (16384 + (b) * 4096)
#define SMEMB   24576

__device__ __forceinline__ uint32_t smem_u32(const void* p) {
    uint32_t a;
    asm("{ .reg .u64 t; cvta.to.shared.u64 t, %1; cvt.u32.u64 %0, t; }" : "=r"(a) : "l"(p));
    return a;
}
__device__ __forceinline__ void ldmA(uint32_t* a, uint32_t saddr) {
    asm volatile("ldmatrix.sync.aligned.m8n8.x4.shared.b16 {%0,%1,%2,%3}, [%4];"
                 : "=r"(a[0]), "=r"(a[1]), "=r"(a[2]), "=r"(a[3]) : "r"(saddr));
}
__device__ __forceinline__ void mma16816(float* d, const uint32_t* a, const uint32_t* b) {
    asm volatile("mma.sync.aligned.m16n8k16.row.col.f32.f16.f16.f32 "
                 "{%0,%1,%2,%3}, {%4,%5,%6,%7}, {%8,%9}, {%0,%1,%2,%3};"
                 : "+f"(d[0]), "+f"(d[1]), "+f"(d[2]), "+f"(d[3])
                 : "r"(a[0]), "r"(a[1]), "r"(a[2]), "r"(a[3]), "r"(b[0]), "r"(b[1]));
}
__device__ __forceinline__ uint32_t f2h2(float a, float b) {
    __half2 h = __floats2half2_rn(a, b);
    return *reinterpret_cast<uint32_t*>(&h);
}
// fast activations: MUFU.TANH (1 MUFU op each)
__device__ __forceinline__ float tanh_f(float x) {
    float r; asm("tanh.approx.f32 %0, %1;" : "=f"(r) : "f"(x)); return r;
}
__device__ __forceinline__ float sigm(float x) {
    return fmaf(0.5f, tanh_f(0.5f * x), 0.5f);
}

__global__ void __launch_bounds__(NTH, 1) lstm2_hmma(
    const float* __restrict__ x,
    const float* __restrict__ Wih0, const float* __restrict__ Whh0,
    const float* __restrict__ bih0, const float* __restrict__ bhh0,
    const float* __restrict__ Wih1, const float* __restrict__ Whh1,
    const float* __restrict__ bih1, const float* __restrict__ bhh1,
    const float* __restrict__ Wfc,  const float* __restrict__ bfc,
    float* __restrict__ out)
{
    __shared__ __align__(16) char sm[SMEMB];
    const uint32_t smb = smem_u32(sm);
    const int tid  = threadIdx.x;
    const int wid  = tid >> 5;          // 0..15, owns 16 gate columns
    const int lane = tid & 31;
    const int tg   = lane & 3;
    const int q    = lane >> 2;
    const int odd  = tg & 1;
    const int batch0 = blockIdx.x * MB;

    // ---- zero h + x regions ----
    for (int i = tid; i < SMEMB / 16; i += NTH) ((uint4*)sm)[i] = make_uint4(0, 0, 0, 0);

    // ---- weight B-fragments into registers (one-time, fp16) ----
    const int n_l = lane >> 2;
    uint32_t Bhh0[4][2][2], Bih1[4][2][2], Bhh1[4][2][2], Bx[2][2];
#pragma unroll
    for (int nt = 0; nt < 2; nt++) {
        const int cg = wid * 16 + nt * 8 + n_l;      // global gate column 0..255
        const int u = cg >> 2, g = cg & 3;
        const float* r0 = Whh0 + (g * 64 + u) * 64;
        const float* r1 = Wih1 + (g * 64 + u) * 64;
        const float* r2 = Whh1 + (g * 64 + u) * 64;
#pragma unroll
        for (int kt = 0; kt < 4; kt++) {
            const int k0 = kt * 16 + tg * 2;
            Bhh0[kt][nt][0] = f2h2(r0[k0],     r0[k0 + 1]);
            Bhh0[kt][nt][1] = f2h2(r0[k0 + 8], r0[k0 + 9]);
            Bih1[kt][nt][0] = f2h2(r1[k0],     r1[k0 + 1]);
            Bih1[kt][nt][1] = f2h2(r1[k0 + 8], r1[k0 + 9]);
            Bhh1[kt][nt][0] = f2h2(r2[k0],     r2[k0 + 1]);
            Bhh1[kt][nt][1] = f2h2(r2[k0 + 8], r2[k0 + 9]);
        }
        const float* rx = Wih0 + (g * 64 + u) * 6;
        const int k0 = tg * 2;
        float w0 = (k0     < 6) ? rx[k0]     : 0.0f;
        float w1 = (k0 + 1 < 6) ? rx[k0 + 1] : 0.0f;
        Bx[nt][0] = f2h2(w0, w1);
        Bx[nt][1] = 0u;
    }
    float b0r[4], b1r[4];
#pragma unroll
    for (int nt = 0; nt < 2; nt++) {
#pragma unroll
        for (int j = 0; j < 2; j++) {
            const int cg = wid * 16 + nt * 8 + tg * 2 + j;
            const int u = cg >> 2, g = cg & 3, idx = g * 64 + u;
            b0r[nt * 2 + j] = bih0[idx] + bhh0[idx];
            b1r[nt * 2 + j] = bih1[idx] + bhh1[idx];
        }
    }

    // ---- stage x(0) ----
    if (tid < MB) {
        const float2* xp = (const float2*)(x + (size_t)(batch0 + tid) * TT * 6);
        float2 a = xp[0], b = xp[1], c = xp[2];
        char* p = sm + XOFF(0) + tid * 128 + ((tid & 7) << 4);
        ((uint32_t*)p)[0] = f2h2(a.x, a.y);
        ((uint32_t*)p)[1] = f2h2(b.x, b.y);
        ((uint32_t*)p)[2] = f2h2(c.x, c.y);
    }
    __syncthreads();

    // ldmatrix lane addressing (A 16x16 tiles from 32x64 fp16, 128B rows, XOR swizzle)
    const uint32_t laneRow  = (uint32_t)(lane & 15);
    const uint32_t sw       = (uint32_t)((lane & 7) << 4);
    const uint32_t col16    = (uint32_t)(lane & 16);
    const uint32_t laneTerm = laneRow * 128;

    float cst0[4], cst1[4];
#pragma unroll
    for (int i = 0; i < 4; i++) { cst0[i] = 0.0f; cst1[i] = 0.0f; }

    float acc[2][2][4];

    for (int t = 0; t < TT; t++) {
        const int cur = t & 1, prv = cur ^ 1;

        // prefetch x(t+1)
        float2 xa, xb, xc;
        if (tid < MB && t + 1 < TT) {
            const float2* xp = (const float2*)(x + ((size_t)(batch0 + tid) * TT + (t + 1)) * 6);
            xa = xp[0]; xb = xp[1]; xc = xp[2];
        }

        // ================= layer 0: gates = b0 + Whh0*h0(prv) + Wih0*x(t) =================
#pragma unroll
        for (int mt = 0; mt < 2; mt++)
#pragma unroll
            for (int nt = 0; nt < 2; nt++) {
                acc[mt][nt][0] = b0r[nt * 2];     acc[mt][nt][1] = b0r[nt * 2 + 1];
                acc[mt][nt][2] = b0r[nt * 2];     acc[mt][nt][3] = b0r[nt * 2 + 1];
            }
        {
            const uint32_t hb = smb + (uint32_t)H0OF(prv) + laneTerm;
#pragma unroll
            for (int kt = 0; kt < 4; kt++) {
                uint32_t a0[4], a1[4];
                const uint32_t coff = (uint32_t)((kt * 32 + col16)) ^ sw;
                ldmA(a0, hb + coff);
                ldmA(a1, hb + 2048 + coff);
#pragma unroll
                for (int nt = 0; nt < 2; nt++) {
                    mma16816(acc[0][nt], a0, Bhh0[kt][nt]);
                    mma16816(acc[1][nt], a1, Bhh0[kt][nt]);
                }
            }
        }
        {   // x contribution (k-tile 0 only)
            const uint32_t xb_ = smb + (uint32_t)XOFF(cur) + laneTerm;
            uint32_t a0[4], a1[4];
            const uint32_t coff = col16 ^ sw;
            ldmA(a0, xb_ + coff);
            ldmA(a1, xb_ + 2048 + coff);
#pragma unroll
            for (int nt = 0; nt < 2; nt++) {
                mma16816(acc[0][nt], a0, Bx[nt]);
                mma16816(acc[1][nt], a1, Bx[nt]);
            }
        }
        // epilogue 0 -> h0[cur]
#pragma unroll
        for (int mt = 0; mt < 2; mt++)
#pragma unroll
            for (int nt = 0; nt < 2; nt++) {
                float* d = acc[mt][nt];
                float s0 = odd ? d[0] : d[2];
                float s1 = odd ? d[1] : d[3];
                float r0 = __shfl_xor_sync(0xffffffffu, s0, 1);
                float r1 = __shfl_xor_sync(0xffffffffu, s1, 1);
                float gi = odd ? r0 : d[0], gf = odd ? r1 : d[1];
                float gg = odd ? d[2] : r0, go = odd ? d[3] : r1;
                float i_ = sigm(gi), f_ = sigm(gf), g_ = tanh_f(gg), o_ = sigm(go);
                float c = fmaf(f_, cst0[mt * 2 + nt], i_ * g_);
                cst0[mt * 2 + nt] = c;
                float h = o_ * tanh_f(c);
                const int u   = wid * 4 + nt * 2 + (tg >> 1);
                const int row = mt * 16 + q + odd * 8;
                const int bo  = row * 128 + ((u * 2) ^ ((row & 7) << 4));
                *(__half*)(sm + H0OF(cur) + bo) = __float2half_rn(h);
            }
        if (tid < MB && t + 1 < TT) {   // publish x(t+1)
            char* p = sm + XOFF(prv) + tid * 128 + ((tid & 7) << 4);
            ((uint32_t*)p)[0] = f2h2(xa.x, xa.y);
            ((uint32_t*)p)[1] = f2h2(xb.x, xb.y);
            ((uint32_t*)p)[2] = f2h2(xc.x, xc.y);
        }
        __syncthreads();

        // ================= layer 1: gates = b1 + Wih1*h0(cur) + Whh1*h1(prv) =================
#pragma unroll
        for (int mt = 0; mt < 2; mt++)
#pragma unroll
            for (int nt = 0; nt < 2; nt++) {
                acc[mt][nt][0] = b1r[nt * 2];     acc[mt][nt][1] = b1r[nt * 2 + 1];
                acc[mt][nt][2] = b1r[nt * 2];     acc[mt][nt][3] = b1r[nt * 2 + 1];
            }
#pragma unroll
        for (int pass = 0; pass < 2; pass++) {
            const uint32_t hb = smb + (pass == 0 ? (uint32_t)H0OF(cur) : (uint32_t)H1OF(prv)) + laneTerm;
#pragma unroll
            for (int kt = 0; kt < 4; kt++) {
                uint32_t a0[4], a1[4];
                const uint32_t coff = (uint32_t)((kt * 32 + col16)) ^ sw;
                ldmA(a0, hb + coff);
                ldmA(a1, hb + 2048 + coff);
#pragma unroll
                for (int nt = 0; nt < 2; nt++) {
                    const uint32_t* B = (pass == 0) ? Bih1[kt][nt] : Bhh1[kt][nt];
                    mma16816(acc[0][nt], a0, B);
                    mma16816(acc[1][nt], a1, B);
                }
            }
        }
        // epilogue 1 -> h1[cur]
#pragma unroll
        for (int mt = 0; mt < 2; mt++)
#pragma unroll
            for (int nt = 0; nt < 2; nt++) {
                float* d = acc[mt][nt];
                float s0 = odd ? d[0] : d[2];
                float s1 = odd ? d[1] : d[3];
                float r0 = __shfl_xor_sync(0xffffffffu, s0, 1);
                float r1 = __shfl_xor_sync(0xffffffffu, s1, 1);
                float gi = odd ? r0 : d[0], gf = odd ? r1 : d[1];
                float gg = odd ? d[2] : r0, go = odd ? d[3] : r1;
                float i_ = sigm(gi), f_ = sigm(gf), g_ = tanh_f(gg), o_ = sigm(go);
                float c = fmaf(f_, cst1[mt * 2 + nt], i_ * g_);
                cst1[mt * 2 + nt] = c;
                float h = o_ * tanh_f(c);
                const int u   = wid * 4 + nt * 2 + (tg >> 1);
                const int row = mt * 16 + q + odd * 8;
                const int bo  = row * 128 + ((u * 2) ^ ((row & 7) << 4));
                *(__half*)(sm + H1OF(cur) + bo) = __float2half_rn(h);
            }
        __syncthreads();
    }

    // ---- final FC from h1[(TT-1)&1 = 1]: out = h1 @ Wfc^T + bfc ----
    if (tid < MB * 3) {
        const int b = tid / 3, oc = tid - b * 3;
        float s = bfc[oc];
#pragma unroll 8
        for (int u = 0; u < 64; u++) {
            const int bo = b * 128 + ((u * 2) ^ ((b & 7) << 4));
            float h = __half2float(*(const __half*)(sm + H1OF(1) + bo));
            s = fmaf(h, Wfc[oc * 64 + u], s);
        }
        out[(size_t)(batch0 + b) * 3 + oc] = s;
    }
}

extern "C" void kernel_launch(void* const* d_in, const int* in_sizes, int n_in,
                              void* d_out, int out_size)
{
    (void)in_sizes; (void)n_in; (void)out_size;
    lstm2_hmma<<<GRID, NTH>>>(
        (const float*)d_in[0],
        (const float*)d_in[1], (const float*)d_in[2],
        (const float*)d_in[3], (const float*)d_in[4],
        (const float*)d_in[5], (const float*)d_in[6],
        (const float*)d_in[7], (const float*)d_in[8],
        (const float*)d_in[9], (const float*)d_in[10],
        (float*)d_out);
}

// round 17
// speedup vs baseline: 1.8197x; 1.0383x over previous
#include <cuda_runtime.h>
#include <cuda_fp16.h>
#include <cstdint>
#include <cstddef>

#define TT   512
#define MB   32
#define NTH  512
#define GRID 128

// ---- smem layout: h tiles 32 rows x 64 units fp16, 128B rows, XOR-swizzled ----
#define H0OF(b) ((b) * 4096)
#define H1OF(b) (8192 + (b) * 4096)
#define XOFF(b) (16384 + (b) * 4096)
#define BOFF0   24576
#define BOFF1   25600
#define SMEMB   26624

__device__ __forceinline__ uint32_t smem_u32(const void* p) {
    uint32_t a;
    asm("{ .reg .u64 t; cvta.to.shared.u64 t, %1; cvt.u32.u64 %0, t; }" : "=r"(a) : "l"(p));
    return a;
}
__device__ __forceinline__ void ldmA(uint32_t* a, uint32_t saddr) {
    asm volatile("ldmatrix.sync.aligned.m8n8.x4.shared.b16 {%0,%1,%2,%3}, [%4];"
                 : "=r"(a[0]), "=r"(a[1]), "=r"(a[2]), "=r"(a[3]) : "r"(saddr));
}
__device__ __forceinline__ void ldmA2(uint32_t* a, uint32_t saddr) {
    asm volatile("ldmatrix.sync.aligned.m8n8.x2.shared.b16 {%0,%1}, [%2];"
                 : "=r"(a[0]), "=r"(a[1]) : "r"(saddr));
}
__device__ __forceinline__ void mma16816(float* d, const uint32_t* a, const uint32_t* b) {
    asm volatile("mma.sync.aligned.m16n8k16.row.col.f32.f16.f16.f32 "
                 "{%0,%1,%2,%3}, {%4,%5,%6,%7}, {%8,%9}, {%0,%1,%2,%3};"
                 : "+f"(d[0]), "+f"(d[1]), "+f"(d[2]), "+f"(d[3])
                 : "r"(a[0]), "r"(a[1]), "r"(a[2]), "r"(a[3]), "r"(b[0]), "r"(b[1]));
}
__device__ __forceinline__ void mma1688(float* d, const uint32_t* a, uint32_t b) {
    asm volatile("mma.sync.aligned.m16n8k8.row.col.f32.f16.f16.f32 "
                 "{%0,%1,%2,%3}, {%4,%5}, {%6}, {%0,%1,%2,%3};"
                 : "+f"(d[0]), "+f"(d[1]), "+f"(d[2]), "+f"(d[3])
                 : "r"(a[0]), "r"(a[1]), "r"(b));
}
__device__ __forceinline__ uint32_t f2h2(float a, float b) {
    __half2 h = __floats2half2_rn(a, b);
    return *reinterpret_cast<uint32_t*>(&h);
}
__device__ __forceinline__ float tanh_f(float x) {
    float r; asm("tanh.approx.f32 %0, %1;" : "=f"(r) : "f"(x)); return r;
}
__device__ __forceinline__ float sigm(float x) {
    return fmaf(0.5f, tanh_f(0.5f * x), 0.5f);
}

__global__ void __launch_bounds__(NTH, 1) lstm2_hmma(
    const float* __restrict__ x,
    const float* __restrict__ Wih0, const float* __restrict__ Whh0,
    const float* __restrict__ bih0, const float* __restrict__ bhh0,
    const float* __restrict__ Wih1, const float* __restrict__ Whh1,
    const float* __restrict__ bih1, const float* __restrict__ bhh1,
    const float* __restrict__ Wfc,  const float* __restrict__ bfc,
    float* __restrict__ out)
{
    __shared__ __align__(16) char sm[SMEMB];
    const uint32_t smb = smem_u32(sm);
    const int tid  = threadIdx.x;
    const int wid  = tid >> 5;          // 0..15, owns 16 gate columns
    const int lane = tid & 31;
    const int tg   = lane & 3;
    const int q    = lane >> 2;
    const int odd  = tg & 1;
    const int batch0 = blockIdx.x * MB;

    // ---- zero h + x regions ----
    for (int i = tid; i < SMEMB / 16; i += NTH) ((uint4*)sm)[i] = make_uint4(0, 0, 0, 0);

    // ---- weight B-fragments into registers (one-time, fp16) ----
    const int n_l = lane >> 2;
    uint32_t Bhh0[4][2][2], Bih1[4][2][2], Bhh1[4][2][2], Bx[2];
#pragma unroll
    for (int nt = 0; nt < 2; nt++) {
        const int cg = wid * 16 + nt * 8 + n_l;      // global gate column 0..255
        const int u = cg >> 2, g = cg & 3;
        const float* r0 = Whh0 + (g * 64 + u) * 64;
        const float* r1 = Wih1 + (g * 64 + u) * 64;
        const float* r2 = Whh1 + (g * 64 + u) * 64;
#pragma unroll
        for (int kt = 0; kt < 4; kt++) {
            const int k0 = kt * 16 + tg * 2;
            Bhh0[kt][nt][0] = f2h2(r0[k0],     r0[k0 + 1]);
            Bhh0[kt][nt][1] = f2h2(r0[k0 + 8], r0[k0 + 9]);
            Bih1[kt][nt][0] = f2h2(r1[k0],     r1[k0 + 1]);
            Bih1[kt][nt][1] = f2h2(r1[k0 + 8], r1[k0 + 9]);
            Bhh1[kt][nt][0] = f2h2(r2[k0],     r2[k0 + 1]);
            Bhh1[kt][nt][1] = f2h2(r2[k0 + 8], r2[k0 + 9]);
        }
        const float* rx = Wih0 + (g * 64 + u) * 6;
        const int k0 = tg * 2;
        float w0 = (k0     < 6) ? rx[k0]     : 0.0f;
        float w1 = (k0 + 1 < 6) ? rx[k0 + 1] : 0.0f;
        Bx[nt] = f2h2(w0, w1);                       // k8 B-frag (k 0..7)
    }
    // summed biases -> smem (gate-column order)
    for (int n = tid; n < 256; n += NTH) {
        const int u = n >> 2, g = n & 3, idx = g * 64 + u;
        ((float*)(sm + BOFF0))[n] = bih0[idx] + bhh0[idx];
        ((float*)(sm + BOFF1))[n] = bih1[idx] + bhh1[idx];
    }

    // ---- stage x(0), x(1) ----
    if (tid < MB) {
        const float2* xp = (const float2*)(x + (size_t)(batch0 + tid) * TT * 6);
        char* p0 = sm + XOFF(0) + tid * 128 + ((tid & 7) << 4);
        ((uint32_t*)p0)[0] = f2h2(xp[0].x, xp[0].y);
        ((uint32_t*)p0)[1] = f2h2(xp[1].x, xp[1].y);
        ((uint32_t*)p0)[2] = f2h2(xp[2].x, xp[2].y);
        char* p1 = sm + XOFF(1) + tid * 128 + ((tid & 7) << 4);
        ((uint32_t*)p1)[0] = f2h2(xp[3].x, xp[3].y);
        ((uint32_t*)p1)[1] = f2h2(xp[4].x, xp[4].y);
        ((uint32_t*)p1)[2] = f2h2(xp[5].x, xp[5].y);
    }
    __syncthreads();

    // ldmatrix lane addressing (A tiles from 32x64 fp16, 128B rows, XOR swizzle)
    const uint32_t laneRow  = (uint32_t)(lane & 15);
    const uint32_t sw       = (uint32_t)((lane & 7) << 4);
    const uint32_t col16    = (uint32_t)(lane & 16);
    const uint32_t laneTerm = laneRow * 128;

    // bias addresses for my 4 columns (2 per n-tile)
    const int bcol0 = wid * 16 + tg * 2;
    const float2 b0a = *(const float2*)(sm + BOFF0 + bcol0 * 4);
    const float2 b0b = *(const float2*)(sm + BOFF0 + (bcol0 + 8) * 4);
    const float2 b1a = *(const float2*)(sm + BOFF1 + bcol0 * 4);
    const float2 b1b = *(const float2*)(sm + BOFF1 + (bcol0 + 8) * 4);

    float cst0[4], cst1[4];
#pragma unroll
    for (int i = 0; i < 4; i++) { cst0[i] = 0.0f; cst1[i] = 0.0f; }

    // h-store offset pieces (per epilogue cell)
    // u = wid*4 + nt*2 + (tg>>1); row = mt*16 + q + odd*8

    // ================= prologue: L0(0) = b0 + Wih0*x(0) =================
    {
        float acc0[2][2][4];
#pragma unroll
        for (int mt = 0; mt < 2; mt++) {
            acc0[mt][0][0] = b0a.x; acc0[mt][0][1] = b0a.y; acc0[mt][0][2] = b0a.x; acc0[mt][0][3] = b0a.y;
            acc0[mt][1][0] = b0b.x; acc0[mt][1][1] = b0b.y; acc0[mt][1][2] = b0b.x; acc0[mt][1][3] = b0b.y;
        }
        const uint32_t xb_ = smb + (uint32_t)XOFF(0) + laneTerm + sw;
        uint32_t a0[2], a1[2];
        ldmA2(a0, xb_);
        ldmA2(a1, xb_ + 2048);
#pragma unroll
        for (int nt = 0; nt < 2; nt++) { mma1688(acc0[0][nt], a0, Bx[nt]); mma1688(acc0[1][nt], a1, Bx[nt]); }
        // epi0(0) -> h0[buf0]
#pragma unroll
        for (int mt = 0; mt < 2; mt++)
#pragma unroll
            for (int nt = 0; nt < 2; nt++) {
                float* d = acc0[mt][nt];
                float s0 = odd ? d[0] : d[2], s1 = odd ? d[1] : d[3];
                float r0 = __shfl_xor_sync(0xffffffffu, s0, 1);
                float r1 = __shfl_xor_sync(0xffffffffu, s1, 1);
                float gi = odd ? r0 : d[0], gf = odd ? r1 : d[1];
                float gg = odd ? d[2] : r0, go = odd ? d[3] : r1;
                float i_ = sigm(gi), f_ = sigm(gf), g_ = tanh_f(gg), o_ = sigm(go);
                float c = fmaf(f_, cst0[mt * 2 + nt], i_ * g_);
                cst0[mt * 2 + nt] = c;
                float h = o_ * tanh_f(c);
                const int u   = wid * 4 + nt * 2 + (tg >> 1);
                const int row = mt * 16 + q + odd * 8;
                const int bo  = row * 128 + ((u * 2) ^ ((row & 7) << 4));
                *(__half*)(sm + H0OF(0) + bo) = __float2half_rn(h);
            }
    }
    __syncthreads();

    // ================= main loop: i handles L1(i) and L0(i+1), ONE sync =================
    float acc1[2][2][4], acc0[2][2][4];
    for (int i = 0; i < TT - 1; i++) {
        const int cur = i & 1, nxt = cur ^ 1;

        // prefetch x(i+2) from gmem (hidden behind gemms)
        float2 xa, xb, xc;
        const bool px = (tid < MB) && (i + 2 < TT);
        if (px) {
            const float2* xp = (const float2*)(x + ((size_t)(batch0 + tid) * TT + (i + 2)) * 6);
            xa = xp[0]; xb = xp[1]; xc = xp[2];
        }

        // init accumulators with biases
#pragma unroll
        for (int mt = 0; mt < 2; mt++) {
            acc1[mt][0][0] = b1a.x; acc1[mt][0][1] = b1a.y; acc1[mt][0][2] = b1a.x; acc1[mt][0][3] = b1a.y;
            acc1[mt][1][0] = b1b.x; acc1[mt][1][1] = b1b.y; acc1[mt][1][2] = b1b.x; acc1[mt][1][3] = b1b.y;
            acc0[mt][0][0] = b0a.x; acc0[mt][0][1] = b0a.y; acc0[mt][0][2] = b0a.x; acc0[mt][0][3] = b0a.y;
            acc0[mt][1][0] = b0b.x; acc0[mt][1][1] = b0b.y; acc0[mt][1][2] = b0b.x; acc0[mt][1][3] = b0b.y;
        }

        // shared-A pass over h0(i) [buf cur]: feeds Bih1 -> acc1 AND Bhh0 -> acc0
        {
            const uint32_t hb = smb + (uint32_t)H0OF(cur) + laneTerm;
#pragma unroll
            for (int kt = 0; kt < 4; kt++) {
                uint32_t a0[4], a1[4];
                const uint32_t coff = (uint32_t)((kt * 32 + col16)) ^ sw;
                ldmA(a0, hb + coff);
                ldmA(a1, hb + 2048 + coff);
#pragma unroll
                for (int nt = 0; nt < 2; nt++) {
                    mma16816(acc1[0][nt], a0, Bih1[kt][nt]);
                    mma16816(acc1[1][nt], a1, Bih1[kt][nt]);
                    mma16816(acc0[0][nt], a0, Bhh0[kt][nt]);
                    mma16816(acc0[1][nt], a1, Bhh0[kt][nt]);
                }
            }
        }
        // x(i+1) pass [buf nxt] (K=8) -> acc0
        {
            const uint32_t xb_ = smb + (uint32_t)XOFF(nxt) + laneTerm + sw;
            uint32_t a0[2], a1[2];
            ldmA2(a0, xb_);
            ldmA2(a1, xb_ + 2048);
#pragma unroll
            for (int nt = 0; nt < 2; nt++) { mma1688(acc0[0][nt], a0, Bx[nt]); mma1688(acc0[1][nt], a1, Bx[nt]); }
        }
        // h1(i-1) pass [buf nxt] -> acc1
        {
            const uint32_t hb = smb + (uint32_t)H1OF(nxt) + laneTerm;
#pragma unroll
            for (int kt = 0; kt < 4; kt++) {
                uint32_t a0[4], a1[4];
                const uint32_t coff = (uint32_t)((kt * 32 + col16)) ^ sw;
                ldmA(a0, hb + coff);
                ldmA(a1, hb + 2048 + coff);
#pragma unroll
                for (int nt = 0; nt < 2; nt++) {
                    mma16816(acc1[0][nt], a0, Bhh1[kt][nt]);
                    mma16816(acc1[1][nt], a1, Bhh1[kt][nt]);
                }
            }
        }

        // ---- epilogues: epi1(i) -> h1[cur], epi0(i+1) -> h0[nxt] ----
#pragma unroll
        for (int mt = 0; mt < 2; mt++)
#pragma unroll
            for (int nt = 0; nt < 2; nt++) {
                const int u   = wid * 4 + nt * 2 + (tg >> 1);
                const int row = mt * 16 + q + odd * 8;
                const int bo  = row * 128 + ((u * 2) ^ ((row & 7) << 4));
                {   // layer 1, step i
                    float* d = acc1[mt][nt];
                    float s0 = odd ? d[0] : d[2], s1 = odd ? d[1] : d[3];
                    float r0 = __shfl_xor_sync(0xffffffffu, s0, 1);
                    float r1 = __shfl_xor_sync(0xffffffffu, s1, 1);
                    float gi = odd ? r0 : d[0], gf = odd ? r1 : d[1];
                    float gg = odd ? d[2] : r0, go = odd ? d[3] : r1;
                    float i_ = sigm(gi), f_ = sigm(gf), g_ = tanh_f(gg), o_ = sigm(go);
                    float c = fmaf(f_, cst1[mt * 2 + nt], i_ * g_);
                    cst1[mt * 2 + nt] = c;
                    *(__half*)(sm + H1OF(cur) + bo) = __float2half_rn(o_ * tanh_f(c));
                }
                {   // layer 0, step i+1
                    float* d = acc0[mt][nt];
                    float s0 = odd ? d[0] : d[2], s1 = odd ? d[1] : d[3];
                    float r0 = __shfl_xor_sync(0xffffffffu, s0, 1);
                    float r1 = __shfl_xor_sync(0xffffffffu, s1, 1);
                    float gi = odd ? r0 : d[0], gf = odd ? r1 : d[1];
                    float gg = odd ? d[2] : r0, go = odd ? d[3] : r1;
                    float i_ = sigm(gi), f_ = sigm(gf), g_ = tanh_f(gg), o_ = sigm(go);
                    float c = fmaf(f_, cst0[mt * 2 + nt], i_ * g_);
                    cst0[mt * 2 + nt] = c;
                    *(__half*)(sm + H0OF(nxt) + bo) = __float2half_rn(o_ * tanh_f(c));
                }
            }
        if (px) {   // publish x(i+2) into x[cur]
            char* p = sm + XOFF(cur) + tid * 128 + ((tid & 7) << 4);
            ((uint32_t*)p)[0] = f2h2(xa.x, xa.y);
            ((uint32_t*)p)[1] = f2h2(xb.x, xb.y);
            ((uint32_t*)p)[2] = f2h2(xc.x, xc.y);
        }
        __syncthreads();
    }

    // ================= tail: L1(TT-1) =================
    {
        const int cur = (TT - 1) & 1;         // = 1
        const int prv = cur ^ 1;
#pragma unroll
        for (int mt = 0; mt < 2; mt++) {
            acc1[mt][0][0] = b1a.x; acc1[mt][0][1] = b1a.y; acc1[mt][0][2] = b1a.x; acc1[mt][0][3] = b1a.y;
            acc1[mt][1][0] = b1b.x; acc1[mt][1][1] = b1b.y; acc1[mt][1][2] = b1b.x; acc1[mt][1][3] = b1b.y;
        }
#pragma unroll
        for (int pass = 0; pass < 2; pass++) {
            const uint32_t hb = smb + (pass == 0 ? (uint32_t)H0OF(cur) : (uint32_t)H1OF(prv)) + laneTerm;
#pragma unroll
            for (int kt = 0; kt < 4; kt++) {
                uint32_t a0[4], a1[4];
                const uint32_t coff = (uint32_t)((kt * 32 + col16)) ^ sw;
                ldmA(a0, hb + coff);
                ldmA(a1, hb + 2048 + coff);
#pragma unroll
                for (int nt = 0; nt < 2; nt++) {
                    const uint32_t* B = (pass == 0) ? Bih1[kt][nt] : Bhh1[kt][nt];
                    mma16816(acc1[0][nt], a0, B);
                    mma16816(acc1[1][nt], a1, B);
                }
            }
        }
#pragma unroll
        for (int mt = 0; mt < 2; mt++)
#pragma unroll
            for (int nt = 0; nt < 2; nt++) {
                float* d = acc1[mt][nt];
                float s0 = odd ? d[0] : d[2], s1 = odd ? d[1] : d[3];
                float r0 = __shfl_xor_sync(0xffffffffu, s0, 1);
                float r1 = __shfl_xor_sync(0xffffffffu, s1, 1);
                float gi = odd ? r0 : d[0], gf = odd ? r1 : d[1];
                float gg = odd ? d[2] : r0, go = odd ? d[3] : r1;
                float i_ = sigm(gi), f_ = sigm(gf), g_ = tanh_f(gg), o_ = sigm(go);
                float c = fmaf(f_, cst1[mt * 2 + nt], i_ * g_);
                float h = o_ * tanh_f(c);
                const int u   = wid * 4 + nt * 2 + (tg >> 1);
                const int row = mt * 16 + q + odd * 8;
                const int bo  = row * 128 + ((u * 2) ^ ((row & 7) << 4));
                *(__half*)(sm + H1OF(cur) + bo) = __float2half_rn(h);
            }
    }
    __syncthreads();

    // ---- final FC from h1(TT-1) [buf 1]: out = h1 @ Wfc^T + bfc ----
    if (tid < MB * 3) {
        const int b = tid / 3, oc = tid - b * 3;
        float s = bfc[oc];
#pragma unroll 8
        for (int u = 0; u < 64; u++) {
            const int bo = b * 128 + ((u * 2) ^ ((b & 7) << 4));
            float h = __half2float(*(const __half*)(sm + H1OF(1) + bo));
            s = fmaf(h, Wfc[oc * 64 + u], s);
        }
        out[(size_t)(batch0 + b) * 3 + oc] = s;
    }
}

extern "C" void kernel_launch(void* const* d_in, const int* in_sizes, int n_in,
                              void* d_out, int out_size)
{
    (void)in_sizes; (void)n_in; (void)out_size;
    lstm2_hmma<<<GRID, NTH>>>(
        (const float*)d_in[0],
        (const float*)d_in[1], (const float*)d_in[2],
        (const float*)d_in[3], (const float*)d_in[4],
        (const float*)d_in[5], (const float*)d_in[6],
        (const float*)d_in[7], (const float*)d_in[8],
        (const float*)d_in[9], (const float*)d_in[10],
        (float*)d_out);
}